// round 3
// baseline (speedup 1.0000x reference)
#include <cuda_runtime.h>
#include <cstddef>

// Problem constants
#define TB 2
#define TT 2048
#define TC 1024
#define TH 16
#define THD 64
#define BT_ROWS (TB*TT)   // 4096
#define FF (4*TC)         // 4096

// Scratch (allocation-free rule: __device__ globals)
__device__ float g_q   [BT_ROWS * TC];
__device__ float g_k   [BT_ROWS * TC];
__device__ float g_v   [BT_ROWS * TC];
__device__ float g_ocat[BT_ROWS * TC];
__device__ float g_x1  [BT_ROWS * TC];
__device__ float g_t2  [BT_ROWS * TC];
__device__ float g_hbuf[(size_t)BT_ROWS * FF];

// ---------------------------------------------------------------------------
// SGEMM core: 128x128 tile, BK=8, 256 threads, 8x8 microtile, reg prefetch.
// ---------------------------------------------------------------------------
template<bool HEADED>
__device__ __forceinline__
void sgemm_body(const float* __restrict__ A, const float* __restrict__ B,
                float* __restrict__ Cc, int N, int K,
                const float* __restrict__ bias, const float* __restrict__ resid,
                int relu, int bm, int bn)
{
    __shared__ float As[8][128];
    __shared__ float Bs[8][128];

    const int tid  = threadIdx.x;
    const int arow = tid >> 1, acol = (tid & 1) * 4;
    const int brow = tid >> 5, bcol = (tid & 31) * 4;
    const int ty   = tid >> 4, tx = tid & 15;
    const int row0 = ty * 8;
    const int ca   = tx * 4;   // owns cols [ca..ca+3] and [64+ca..64+ca+3]

    const float* Aptr = A + (size_t)(bm + arow) * K + acol;

    const float* Bbase;
    size_t bstride;
    if (HEADED) {
        int j = bn + bcol;
        Bbase   = B + (size_t)(j >> 6) * ((size_t)K * 64) + (j & 63);
        bstride = 64;
    } else {
        Bbase   = B + bn + bcol;
        bstride = (size_t)N;
    }

    float acc[8][8];
    #pragma unroll
    for (int i = 0; i < 8; i++)
        #pragma unroll
        for (int j = 0; j < 8; j++) acc[i][j] = 0.f;

    const int nk = K >> 3;
    float4 a4 = *reinterpret_cast<const float4*>(Aptr);
    float4 b4 = *reinterpret_cast<const float4*>(Bbase + (size_t)brow * bstride);

    for (int t = 0;;) {
        As[acol + 0][arow] = a4.x;
        As[acol + 1][arow] = a4.y;
        As[acol + 2][arow] = a4.z;
        As[acol + 3][arow] = a4.w;
        *reinterpret_cast<float4*>(&Bs[brow][bcol]) = b4;
        __syncthreads();

        ++t;
        if (t < nk) {
            a4 = *reinterpret_cast<const float4*>(Aptr + (size_t)t * 8);
            b4 = *reinterpret_cast<const float4*>(Bbase + (size_t)(t * 8 + brow) * bstride);
        }

        #pragma unroll
        for (int k = 0; k < 8; k++) {
            float a[8], b[8];
            *reinterpret_cast<float4*>(&a[0]) = *reinterpret_cast<const float4*>(&As[k][row0]);
            *reinterpret_cast<float4*>(&a[4]) = *reinterpret_cast<const float4*>(&As[k][row0 + 4]);
            *reinterpret_cast<float4*>(&b[0]) = *reinterpret_cast<const float4*>(&Bs[k][ca]);
            *reinterpret_cast<float4*>(&b[4]) = *reinterpret_cast<const float4*>(&Bs[k][64 + ca]);
            #pragma unroll
            for (int i = 0; i < 8; i++)
                #pragma unroll
                for (int j = 0; j < 8; j++)
                    acc[i][j] = fmaf(a[i], b[j], acc[i][j]);
        }
        if (t == nk) break;
        __syncthreads();
    }

    // epilogue
    #pragma unroll
    for (int i = 0; i < 8; i++) {
        size_t m = (size_t)(bm + row0 + i);
        #pragma unroll
        for (int jh = 0; jh < 2; jh++) {
            int n = bn + jh * 64 + ca;
            float4 v;
            v.x = acc[i][jh * 4 + 0];
            v.y = acc[i][jh * 4 + 1];
            v.z = acc[i][jh * 4 + 2];
            v.w = acc[i][jh * 4 + 3];
            if (bias) {
                float4 bb = *reinterpret_cast<const float4*>(bias + n);
                v.x += bb.x; v.y += bb.y; v.z += bb.z; v.w += bb.w;
            }
            if (resid) {
                float4 rr = *reinterpret_cast<const float4*>(resid + m * N + n);
                v.x += rr.x; v.y += rr.y; v.z += rr.z; v.w += rr.w;
            }
            if (relu) {
                v.x = fmaxf(v.x, 0.f); v.y = fmaxf(v.y, 0.f);
                v.z = fmaxf(v.z, 0.f); v.w = fmaxf(v.w, 0.f);
            }
            *reinterpret_cast<float4*>(Cc + m * N + n) = v;
        }
    }
}

// Generic single-GEMM wrapper
template<bool HEADED>
__global__ __launch_bounds__(256, 2)
void sgemm128(const float* __restrict__ A, const float* __restrict__ B,
              float* __restrict__ Cc, int M, int N, int K,
              const float* __restrict__ bias, const float* __restrict__ resid,
              int relu)
{
    sgemm_body<HEADED>(A, B, Cc, N, K, bias, resid, relu,
                       blockIdx.y * 128, blockIdx.x * 128);
}

// Fused QKV: grid.z selects which of the three headed projections this CTA does.
__global__ __launch_bounds__(256, 2)
void qkv_gemm(const float* __restrict__ X,
              const float* __restrict__ Wq, const float* __restrict__ Wk,
              const float* __restrict__ Wv,
              float* __restrict__ Oq, float* __restrict__ Ok, float* __restrict__ Ov)
{
    const float* W;
    float* O;
    if (blockIdx.z == 0)      { W = Wq; O = Oq; }
    else if (blockIdx.z == 1) { W = Wk; O = Ok; }
    else                      { W = Wv; O = Ov; }
    sgemm_body<true>(X, W, O, TC, TC, nullptr, nullptr, 0,
                     blockIdx.y * 128, blockIdx.x * 128);
}

// ---------------------------------------------------------------------------
// Flash attention (fp32, causal). One block = (64 queries, head h, batch b).
// q/k/v in [B,T,C] head-concat layout. Writes O head-concat.
// ---------------------------------------------------------------------------
#define ATTN_SMEM_FLOATS (64*65*3 + 64*64)

__global__ __launch_bounds__(256)
void attn_kernel(const float* __restrict__ Q, const float* __restrict__ Kg,
                 const float* __restrict__ Vg, float* __restrict__ O)
{
    extern __shared__ float sm[];
    float* Qs = sm;              // [64][65], pre-scaled
    float* Ks = Qs + 64 * 65;    // [64][65]
    float* Vs = Ks + 64 * 65;    // [64][64]
    float* Ps = Vs + 64 * 64;    // [64][65]
    __shared__ float m_s[64], l_s[64], alpha_s[64];
    __shared__ float red[64][17];

    const int tid = threadIdx.x;
    const int tx = tid & 15, ty = tid >> 4;
    const int r0 = ty * 4, c0 = tx * 4;
    const int qt = blockIdx.x;
    const int h  = blockIdx.y;
    const int b  = blockIdx.z;
    const int qbase = qt * 64;

    const float* qb = Q  + (size_t)b * TT * TC + (size_t)h * 64;
    const float* kb = Kg + (size_t)b * TT * TC + (size_t)h * 64;
    const float* vb = Vg + (size_t)b * TT * TC + (size_t)h * 64;

    // Load + scale Q tile
    for (int f = tid; f < 64 * 16; f += 256) {
        int row = f >> 4, dc = (f & 15) * 4;
        float4 t = *reinterpret_cast<const float4*>(qb + (size_t)(qbase + row) * TC + dc);
        float* dst = Qs + row * 65 + dc;
        dst[0] = t.x * 0.125f; dst[1] = t.y * 0.125f;
        dst[2] = t.z * 0.125f; dst[3] = t.w * 0.125f;
    }
    if (tid < 64) { m_s[tid] = -3.0e38f; l_s[tid] = 0.f; }

    float o[4][4];
    #pragma unroll
    for (int i = 0; i < 4; i++)
        #pragma unroll
        for (int j = 0; j < 4; j++) o[i][j] = 0.f;
    __syncthreads();

    for (int jt = 0; jt <= qt; ++jt) {
        const int kvbase = jt * 64;
        // Load K, V tiles
        for (int f = tid; f < 64 * 16; f += 256) {
            int row = f >> 4, dc = (f & 15) * 4;
            float4 tk = *reinterpret_cast<const float4*>(kb + (size_t)(kvbase + row) * TC + dc);
            float* dk = Ks + row * 65 + dc;
            dk[0] = tk.x; dk[1] = tk.y; dk[2] = tk.z; dk[3] = tk.w;
            float4 tv = *reinterpret_cast<const float4*>(vb + (size_t)(kvbase + row) * TC + dc);
            *reinterpret_cast<float4*>(Vs + row * 64 + dc) = tv;
        }
        __syncthreads();

        // S = Qs @ Ks^T  (4x4 per thread)
        float s[4][4];
        #pragma unroll
        for (int i = 0; i < 4; i++)
            #pragma unroll
            for (int j = 0; j < 4; j++) s[i][j] = 0.f;

        #pragma unroll 8
        for (int dd = 0; dd < 64; ++dd) {
            float qv[4], kv[4];
            #pragma unroll
            for (int i = 0; i < 4; i++) qv[i] = Qs[(r0 + i) * 65 + dd];
            #pragma unroll
            for (int j = 0; j < 4; j++) kv[j] = Ks[(c0 + j) * 65 + dd];
            #pragma unroll
            for (int i = 0; i < 4; i++)
                #pragma unroll
                for (int j = 0; j < 4; j++)
                    s[i][j] = fmaf(qv[i], kv[j], s[i][j]);
        }

        if (jt == qt) {  // causal mask on diagonal tile
            #pragma unroll
            for (int i = 0; i < 4; i++)
                #pragma unroll
                for (int j = 0; j < 4; j++)
                    if (c0 + j > r0 + i) s[i][j] = -3.0e38f;
        }

        // row-max partials
        #pragma unroll
        for (int i = 0; i < 4; i++) {
            float mx = fmaxf(fmaxf(s[i][0], s[i][1]), fmaxf(s[i][2], s[i][3]));
            red[r0 + i][tx] = mx;
        }
        __syncthreads();
        if (tid < 64) {
            float mx = red[tid][0];
            #pragma unroll
            for (int j = 1; j < 16; j++) mx = fmaxf(mx, red[tid][j]);
            float mn = fmaxf(m_s[tid], mx);
            alpha_s[tid] = __expf(m_s[tid] - mn);
            m_s[tid] = mn;
        }
        __syncthreads();

        // P = exp(S - m), stage to smem, row-sum partials
        #pragma unroll
        for (int i = 0; i < 4; i++) {
            float mr = m_s[r0 + i];
            float rs = 0.f;
            #pragma unroll
            for (int j = 0; j < 4; j++) {
                float p = __expf(s[i][j] - mr);
                Ps[(r0 + i) * 65 + c0 + j] = p;
                rs += p;
            }
            red[r0 + i][tx] = rs;
        }
        __syncthreads();
        if (tid < 64) {
            float sum = 0.f;
            #pragma unroll
            for (int j = 0; j < 16; j++) sum += red[tid][j];
            l_s[tid] = l_s[tid] * alpha_s[tid] + sum;
        }

        // O = O*alpha + P @ V
        float al[4];
        #pragma unroll
        for (int i = 0; i < 4; i++) al[i] = alpha_s[r0 + i];
        #pragma unroll
        for (int i = 0; i < 4; i++)
            #pragma unroll
            for (int j = 0; j < 4; j++) o[i][j] *= al[i];

        #pragma unroll 8
        for (int ss = 0; ss < 64; ++ss) {
            float pv[4], vv[4];
            #pragma unroll
            for (int i = 0; i < 4; i++) pv[i] = Ps[(r0 + i) * 65 + ss];
            #pragma unroll
            for (int j = 0; j < 4; j++) vv[j] = Vs[ss * 64 + c0 + j];
            #pragma unroll
            for (int i = 0; i < 4; i++)
                #pragma unroll
                for (int j = 0; j < 4; j++)
                    o[i][j] = fmaf(pv[i], vv[j], o[i][j]);
        }
        __syncthreads();  // protect Ks/Vs/Ps/red for next tile
    }

    float* ob = O + (size_t)b * TT * TC + (size_t)h * 64;
    #pragma unroll
    for (int i = 0; i < 4; i++) {
        float inv = 1.f / l_s[r0 + i];
        #pragma unroll
        for (int j = 0; j < 4; j++)
            ob[(size_t)(qbase + r0 + i) * TC + c0 + j] = o[i][j] * inv;
    }
}

// ---------------------------------------------------------------------------
// LayerNorm: one block per row of C=1024, 256 threads x 4 elems.
// ---------------------------------------------------------------------------
__global__ __launch_bounds__(256)
void ln_kernel(const float* __restrict__ in, float* __restrict__ out,
               const float* __restrict__ g, const float* __restrict__ bta)
{
    const int row = blockIdx.x;
    const int tid = threadIdx.x;
    const float* xr = in + (size_t)row * TC;

    float4 v = *reinterpret_cast<const float4*>(xr + tid * 4);
    float s = v.x + v.y + v.z + v.w;

    __shared__ float sred[8];
    __shared__ float s_mu, s_inv;

    #pragma unroll
    for (int o = 16; o > 0; o >>= 1) s += __shfl_xor_sync(0xffffffffu, s, o);
    if ((tid & 31) == 0) sred[tid >> 5] = s;
    __syncthreads();
    if (tid == 0) {
        float t = 0.f;
        #pragma unroll
        for (int i = 0; i < 8; i++) t += sred[i];
        s_mu = t * (1.f / TC);
    }
    __syncthreads();
    const float mu = s_mu;

    float dx = v.x - mu, dy = v.y - mu, dz = v.z - mu, dw = v.w - mu;
    float q = dx * dx + dy * dy + dz * dz + dw * dw;
    #pragma unroll
    for (int o = 16; o > 0; o >>= 1) q += __shfl_xor_sync(0xffffffffu, q, o);
    if ((tid & 31) == 0) sred[tid >> 5] = q;
    __syncthreads();
    if (tid == 0) {
        float t = 0.f;
        #pragma unroll
        for (int i = 0; i < 8; i++) t += sred[i];
        s_inv = rsqrtf(t * (1.f / TC) + 1e-5f);
    }
    __syncthreads();
    const float inv = s_inv;

    float4 gg = *reinterpret_cast<const float4*>(g   + tid * 4);
    float4 bb = *reinterpret_cast<const float4*>(bta + tid * 4);
    float4 r;
    r.x = dx * inv * gg.x + bb.x;
    r.y = dy * inv * gg.y + bb.y;
    r.z = dz * inv * gg.z + bb.z;
    r.w = dw * inv * gg.w + bb.w;
    *reinterpret_cast<float4*>(out + (size_t)row * TC + tid * 4) = r;
}

// ---------------------------------------------------------------------------
extern "C" void kernel_launch(void* const* d_in, const int* in_sizes, int n_in,
                              void* d_out, int out_size)
{
    const float* x   = (const float*)d_in[0];
    const float* Wq  = (const float*)d_in[1];
    const float* Wk  = (const float*)d_in[2];
    const float* Wv  = (const float*)d_in[3];
    const float* Wp  = (const float*)d_in[4];
    const float* bp  = (const float*)d_in[5];
    const float* W1  = (const float*)d_in[6];
    const float* b1  = (const float*)d_in[7];
    const float* W2  = (const float*)d_in[8];
    const float* b2  = (const float*)d_in[9];
    const float* g1  = (const float*)d_in[10];
    const float* be1 = (const float*)d_in[11];
    const float* g2  = (const float*)d_in[12];
    const float* be2 = (const float*)d_in[13];

    float *q, *k, *v, *ocat, *x1, *t2, *hbuf;
    cudaGetSymbolAddress((void**)&q,    g_q);
    cudaGetSymbolAddress((void**)&k,    g_k);
    cudaGetSymbolAddress((void**)&v,    g_v);
    cudaGetSymbolAddress((void**)&ocat, g_ocat);
    cudaGetSymbolAddress((void**)&x1,   g_x1);
    cudaGetSymbolAddress((void**)&t2,   g_t2);
    cudaGetSymbolAddress((void**)&hbuf, g_hbuf);

    const int attn_smem = ATTN_SMEM_FLOATS * (int)sizeof(float);
    cudaFuncSetAttribute(attn_kernel, cudaFuncAttributeMaxDynamicSharedMemorySize, attn_smem);

    dim3 blk(256);
    dim3 gC(TC / 128, BT_ROWS / 128);      // (8, 32)
    dim3 gF(FF / 128, BT_ROWS / 128);      // (32, 32)
    dim3 gA(TT / 64, TH, TB);              // (32, 16, 2)
    dim3 gQKV(TC / 128, BT_ROWS / 128, 3); // (8, 32, 3) fused QKV

    // QKV projections (headed weights) -> [B,T,C] concat layout, one launch
    qkv_gemm<<<gQKV, blk>>>(x, Wq, Wk, Wv, q, k, v);

    // Causal attention
    attn_kernel<<<gA, blk, attn_smem>>>(q, k, v, ocat);

    // Output projection + bias + residual(x)
    sgemm128<false><<<gC, blk>>>(ocat, Wp, t2, BT_ROWS, TC, TC, bp, x, 0);
    // LN1
    ln_kernel<<<BT_ROWS, blk>>>(t2, x1, g1, be1);
    // FFN
    sgemm128<false><<<gF, blk>>>(x1, W1, hbuf, BT_ROWS, FF, TC, b1, nullptr, 1);
    sgemm128<false><<<gC, blk>>>(hbuf, W2, t2, BT_ROWS, TC, FF, b2, x1, 0);
    // LN2 -> output
    ln_kernel<<<BT_ROWS, blk>>>(t2, (float*)d_out, g2, be2);
}

// round 6
// speedup vs baseline: 1.7102x; 1.7102x over previous
#include <cuda_runtime.h>
#include <cuda_bf16.h>
#include <cstdint>
#include <cstddef>

// ---------------------------------------------------------------------------
// Problem constants
// ---------------------------------------------------------------------------
#define TB 2
#define TT 2048
#define TC 1024
#define TH 16
#define BT_ROWS (TB*TT)     // 4096
#define FF (4*TC)           // 4096
#define ACT (BT_ROWS*TC)    // 4M elements

// ---------------------------------------------------------------------------
// Scratch (__device__ globals; no allocation allowed)
// ---------------------------------------------------------------------------
__device__ float g_q[ACT], g_k[ACT], g_v[ACT], g_ocat[ACT], g_x1[ACT], g_t2[ACT];
__device__ float g_hbuf[(size_t)BT_ROWS * FF];

// bf16 split activations
__device__ __nv_bfloat16 g_xh[ACT],  g_xl[ACT];
__device__ __nv_bfloat16 g_oh[ACT],  g_ol[ACT];
__device__ __nv_bfloat16 g_x1h[ACT], g_x1l[ACT];
__device__ __nv_bfloat16 g_hh[(size_t)BT_ROWS * FF], g_hl[(size_t)BT_ROWS * FF];

// bf16 split transposed weights, layout [N, K] (K-major rows)
__device__ __nv_bfloat16 g_wqh[TC*TC], g_wql[TC*TC];
__device__ __nv_bfloat16 g_wkh[TC*TC], g_wkl[TC*TC];
__device__ __nv_bfloat16 g_wvh[TC*TC], g_wvl[TC*TC];
__device__ __nv_bfloat16 g_wph[TC*TC], g_wpl[TC*TC];
__device__ __nv_bfloat16 g_w1h[TC*FF], g_w1l[TC*FF];
__device__ __nv_bfloat16 g_w2h[TC*FF], g_w2l[TC*FF];

// ---------------------------------------------------------------------------
// PTX helpers: generic compute_103-safe (NO tcgen05 — ptxas target lacks it)
// ---------------------------------------------------------------------------
__device__ __forceinline__ uint32_t smem_u32(const void* p) {
    uint32_t a;
    asm("{ .reg .u64 t; cvta.to.shared.u64 t, %1; cvt.u32.u64 %0, t; }" : "=r"(a) : "l"(p));
    return a;
}
__device__ __forceinline__ void cpa16(uint32_t d, const void* s) {
    asm volatile("cp.async.cg.shared.global [%0], [%1], 16;" :: "r"(d), "l"(s));
}
#define CP_COMMIT() asm volatile("cp.async.commit_group;" ::: "memory")
template<int N_>
__device__ __forceinline__ void cp_wait() {
    asm volatile("cp.async.wait_group %0;" :: "n"(N_) : "memory");
}
__device__ __forceinline__ void ldsm4(uint32_t addr, uint32_t* r) {
    asm volatile("ldmatrix.sync.aligned.m8n8.x4.shared.b16 {%0,%1,%2,%3}, [%4];"
                 : "=r"(r[0]), "=r"(r[1]), "=r"(r[2]), "=r"(r[3]) : "r"(addr));
}
__device__ __forceinline__ void mma16816(float* c, const uint32_t* a, const uint32_t* b) {
    asm volatile("mma.sync.aligned.m16n8k16.row.col.f32.bf16.bf16.f32 "
                 "{%0,%1,%2,%3}, {%4,%5,%6,%7}, {%8,%9}, {%0,%1,%2,%3};"
                 : "+f"(c[0]), "+f"(c[1]), "+f"(c[2]), "+f"(c[3])
                 : "r"(a[0]), "r"(a[1]), "r"(a[2]), "r"(a[3]), "r"(b[0]), "r"(b[1]));
}

#define GSMEM_BYTES 65536   // 2 stages * 4 tiles * 8KB (128x32 bf16 each)

// Load a 128x32 bf16 tile (row stride ldk) into swizzled smem.
// smem layout: byte = row*64 + ((seg ^ ((row>>1)&3)) * 16), seg = k16B-chunk (0-3)
__device__ __forceinline__
void load_tile(uint32_t dst, const __nv_bfloat16* __restrict__ src,
               int row0, int k0, int ldk, int tid)
{
    #pragma unroll
    for (int i = 0; i < 2; ++i) {
        const int idx  = tid + i * 256;       // 0..511
        const int row  = idx >> 2;
        const int seg  = idx & 3;
        const int phys = seg ^ ((row >> 1) & 3);
        cpa16(dst + (uint32_t)(row * 64 + phys * 16),
              src + (size_t)(row0 + row) * ldk + k0 + seg * 8);
    }
}

// ---------------------------------------------------------------------------
// bf16x3 HMMA GEMM: C[128m x 128n] per CTA, BK=32, cp.async double buffer.
// A (hi/lo): [M,K] bf16 K-major. BT (hi/lo): [N,K] bf16 K-major (B col-major).
// D = Ah*Bh + Ah*Bl + Al*Bh, fp32 accumulators.
// ---------------------------------------------------------------------------
__device__ __forceinline__
void gemm_body(const __nv_bfloat16* __restrict__ Ah, const __nv_bfloat16* __restrict__ Al,
               const __nv_bfloat16* __restrict__ BTh, const __nv_bfloat16* __restrict__ BTl,
               float* __restrict__ C, int N, int K,
               const float* __restrict__ bias, const float* __restrict__ resid, int relu)
{
    extern __shared__ char sm[];
    const uint32_t sb = smem_u32(sm);
    const int tid  = threadIdx.x;
    const int lane = tid & 31;
    const int wid  = tid >> 5;
    const int bm   = blockIdx.y * 128;
    const int bn   = blockIdx.x * 128;

    // warp tile: 64(m) x 32(n); warp grid 2x4
    const int wm0 = (wid >> 2) * 64;
    const int wn0 = (wid & 3) * 32;

    // ldmatrix per-lane row indices (invariant under +16/+8 row steps for swizzle bits)
    const uint32_t rowA = (uint32_t)(wm0 + (lane & 15));
    const uint32_t rowB = (uint32_t)(wn0 + (lane & 7) + ((lane >> 4) & 1) * 8);
    const uint32_t swA  = (rowA >> 1) & 3;
    const uint32_t swB  = (rowB >> 1) & 3;
    const uint32_t baA  = rowA * 64;
    const uint32_t baB  = rowB * 64;
    const uint32_t segA = (uint32_t)(lane >> 4);        // 0/1
    const uint32_t segB = (uint32_t)((lane >> 3) & 1);  // 0/1

    float acc[4][4][4];
    #pragma unroll
    for (int i = 0; i < 4; i++)
        #pragma unroll
        for (int j = 0; j < 4; j++)
            #pragma unroll
            for (int q = 0; q < 4; q++) acc[i][j][q] = 0.f;

    auto load_stage = [&](int s, int k0) {
        const uint32_t base = sb + (uint32_t)s * 32768u;
        load_tile(base,          Ah,  bm, k0, K, tid);
        load_tile(base + 8192u,  Al,  bm, k0, K, tid);
        load_tile(base + 16384u, BTh, bn, k0, K, tid);
        load_tile(base + 24576u, BTl, bn, k0, K, tid);
    };

    const int NIT = K >> 5;
    load_stage(0, 0);
    CP_COMMIT();

    for (int it = 0; it < NIT; ++it) {
        if (it + 1 < NIT) {
            load_stage((it + 1) & 1, (it + 1) * 32);
            CP_COMMIT();
            cp_wait<1>();
        } else {
            cp_wait<0>();
        }
        __syncthreads();

        const uint32_t st  = sb + (uint32_t)(it & 1) * 32768u;
        const uint32_t tAh = st,          tAl = st + 8192u;
        const uint32_t tBh = st + 16384u, tBl = st + 24576u;

        #pragma unroll
        for (int ks = 0; ks < 2; ++ks) {
            const uint32_t pA = (((uint32_t)(ks * 2) + segA) ^ swA) * 16u;
            const uint32_t pB = (((uint32_t)(ks * 2) + segB) ^ swB) * 16u;

            uint32_t ah[4][4], al[4][4];
            #pragma unroll
            for (int mi = 0; mi < 4; ++mi) {
                const uint32_t ra = baA + (uint32_t)mi * 1024u;   // +16 rows
                ldsm4(tAh + ra + pA, ah[mi]);
                ldsm4(tAl + ra + pA, al[mi]);
            }
            uint32_t bh[4][2], bl[4][2];
            #pragma unroll
            for (int g = 0; g < 2; ++g) {
                const uint32_t rb = baB + (uint32_t)g * 1024u;    // +16 rows
                uint32_t t[4];
                ldsm4(tBh + rb + pB, t);
                bh[g*2][0] = t[0]; bh[g*2][1] = t[1];
                bh[g*2+1][0] = t[2]; bh[g*2+1][1] = t[3];
                ldsm4(tBl + rb + pB, t);
                bl[g*2][0] = t[0]; bl[g*2][1] = t[1];
                bl[g*2+1][0] = t[2]; bl[g*2+1][1] = t[3];
            }
            #pragma unroll
            for (int mi = 0; mi < 4; ++mi)
                #pragma unroll
                for (int ni = 0; ni < 4; ++ni) {
                    mma16816(acc[mi][ni], ah[mi], bh[ni]);
                    mma16816(acc[mi][ni], ah[mi], bl[ni]);
                    mma16816(acc[mi][ni], al[mi], bh[ni]);
                }
        }
        __syncthreads();
    }

    // Epilogue: fragment (mi,ni): rows bm+wm0+mi*16+{lane>>2, +8}, cols bn+wn0+ni*8+(lane&3)*2
    #pragma unroll
    for (int mi = 0; mi < 4; ++mi) {
        #pragma unroll
        for (int ni = 0; ni < 4; ++ni) {
            const int r  = bm + wm0 + mi * 16 + (lane >> 2);
            const int cn = bn + wn0 + ni * 8 + (lane & 3) * 2;
            float2 v0 = make_float2(acc[mi][ni][0], acc[mi][ni][1]);
            float2 v1 = make_float2(acc[mi][ni][2], acc[mi][ni][3]);
            if (bias) {
                const float2 bb = *reinterpret_cast<const float2*>(bias + cn);
                v0.x += bb.x; v0.y += bb.y; v1.x += bb.x; v1.y += bb.y;
            }
            if (resid) {
                const float2 r0 = *reinterpret_cast<const float2*>(resid + (size_t)r * N + cn);
                const float2 r1 = *reinterpret_cast<const float2*>(resid + (size_t)(r + 8) * N + cn);
                v0.x += r0.x; v0.y += r0.y; v1.x += r1.x; v1.y += r1.y;
            }
            if (relu) {
                v0.x = fmaxf(v0.x, 0.f); v0.y = fmaxf(v0.y, 0.f);
                v1.x = fmaxf(v1.x, 0.f); v1.y = fmaxf(v1.y, 0.f);
            }
            *reinterpret_cast<float2*>(C + (size_t)r * N + cn) = v0;
            *reinterpret_cast<float2*>(C + (size_t)(r + 8) * N + cn) = v1;
        }
    }
}

__global__ __launch_bounds__(256, 1)
void gemm_bf3(const __nv_bfloat16* __restrict__ Ah, const __nv_bfloat16* __restrict__ Al,
              const __nv_bfloat16* __restrict__ BTh, const __nv_bfloat16* __restrict__ BTl,
              float* __restrict__ C, int N, int K,
              const float* __restrict__ bias, const float* __restrict__ resid, int relu)
{
    gemm_body(Ah, Al, BTh, BTl, C, N, K, bias, resid, relu);
}

__global__ __launch_bounds__(256, 1)
void qkv_bf3(const __nv_bfloat16* __restrict__ xh, const __nv_bfloat16* __restrict__ xl,
             const __nv_bfloat16* __restrict__ wqh, const __nv_bfloat16* __restrict__ wql,
             const __nv_bfloat16* __restrict__ wkh, const __nv_bfloat16* __restrict__ wkl,
             const __nv_bfloat16* __restrict__ wvh, const __nv_bfloat16* __restrict__ wvl,
             float* __restrict__ q, float* __restrict__ k, float* __restrict__ v)
{
    const __nv_bfloat16 *bh, *bl;
    float* out;
    if (blockIdx.z == 0)      { bh = wqh; bl = wql; out = q; }
    else if (blockIdx.z == 1) { bh = wkh; bl = wkl; out = k; }
    else                      { bh = wvh; bl = wvl; out = v; }
    gemm_body(xh, xl, bh, bl, out, TC, TC, nullptr, nullptr, 0);
}

// ---------------------------------------------------------------------------
// fp32 -> bf16 hi/lo split (elementwise)
// ---------------------------------------------------------------------------
__global__ __launch_bounds__(256)
void cvt_split(const float* __restrict__ in, __nv_bfloat16* __restrict__ hi,
               __nv_bfloat16* __restrict__ lo, int n4)
{
    const int i = blockIdx.x * 256 + threadIdx.x;
    if (i >= n4) return;
    const float4 v = reinterpret_cast<const float4*>(in)[i];
    float f[4] = {v.x, v.y, v.z, v.w};
    __nv_bfloat16 h[4], l[4];
    #pragma unroll
    for (int j = 0; j < 4; j++) {
        h[j] = __float2bfloat16(f[j]);
        l[j] = __float2bfloat16(f[j] - __bfloat162float(h[j]));
    }
    __nv_bfloat162* hp = reinterpret_cast<__nv_bfloat162*>(hi + (size_t)i * 4);
    __nv_bfloat162* lp = reinterpret_cast<__nv_bfloat162*>(lo + (size_t)i * 4);
    hp[0] = __halves2bfloat162(h[0], h[1]);
    hp[1] = __halves2bfloat162(h[2], h[3]);
    lp[0] = __halves2bfloat162(l[0], l[1]);
    lp[1] = __halves2bfloat162(l[2], l[3]);
}

// ---------------------------------------------------------------------------
// Weight transpose + split: W[K,N] (or headed [H,K,64]) -> T[N,K] bf16 hi/lo
// ---------------------------------------------------------------------------
template<bool HEADED>
__global__ __launch_bounds__(256)
void transpose_split(const float* __restrict__ W, __nv_bfloat16* __restrict__ Th,
                     __nv_bfloat16* __restrict__ Tl, int K, int N)
{
    __shared__ float ts[32][33];
    const int n0 = blockIdx.x * 32;
    const int k0 = blockIdx.y * 32;
    const int tx = threadIdx.x & 31;
    const int ty = threadIdx.x >> 5;    // 0..7
    #pragma unroll
    for (int i = ty; i < 32; i += 8) {
        const int n = n0 + tx, k = k0 + i;
        const float v = HEADED ? W[((size_t)(n >> 6) * K + k) * 64 + (n & 63)]
                               : W[(size_t)k * N + n];
        ts[i][tx] = v;
    }
    __syncthreads();
    #pragma unroll
    for (int i = ty; i < 32; i += 8) {
        const int n = n0 + i, k = k0 + tx;
        const float v = ts[tx][i];
        const __nv_bfloat16 h = __float2bfloat16(v);
        const __nv_bfloat16 l = __float2bfloat16(v - __bfloat162float(h));
        Th[(size_t)n * K + k] = h;
        Tl[(size_t)n * K + k] = l;
    }
}

// ---------------------------------------------------------------------------
// Flash attention (fp32, causal) — unchanged from passing round-3 kernel
// ---------------------------------------------------------------------------
#define ATTN_SMEM_FLOATS (64*65*3 + 64*64)

__global__ __launch_bounds__(256)
void attn_kernel(const float* __restrict__ Q, const float* __restrict__ Kg,
                 const float* __restrict__ Vg, float* __restrict__ O)
{
    extern __shared__ float smf[];
    float* Qs = smf;
    float* Ks = Qs + 64 * 65;
    float* Vs = Ks + 64 * 65;
    float* Ps = Vs + 64 * 64;
    __shared__ float m_s[64], l_s[64], alpha_s[64];
    __shared__ float red[64][17];

    const int tid = threadIdx.x;
    const int tx = tid & 15, ty = tid >> 4;
    const int r0 = ty * 4, c0 = tx * 4;
    const int qt = blockIdx.x;
    const int h  = blockIdx.y;
    const int b  = blockIdx.z;
    const int qbase = qt * 64;

    const float* qb = Q  + (size_t)b * TT * TC + (size_t)h * 64;
    const float* kb = Kg + (size_t)b * TT * TC + (size_t)h * 64;
    const float* vb = Vg + (size_t)b * TT * TC + (size_t)h * 64;

    for (int f = tid; f < 64 * 16; f += 256) {
        int row = f >> 4, dc = (f & 15) * 4;
        float4 t = *reinterpret_cast<const float4*>(qb + (size_t)(qbase + row) * TC + dc);
        float* dst = Qs + row * 65 + dc;
        dst[0] = t.x * 0.125f; dst[1] = t.y * 0.125f;
        dst[2] = t.z * 0.125f; dst[3] = t.w * 0.125f;
    }
    if (tid < 64) { m_s[tid] = -3.0e38f; l_s[tid] = 0.f; }

    float o[4][4];
    #pragma unroll
    for (int i = 0; i < 4; i++)
        #pragma unroll
        for (int j = 0; j < 4; j++) o[i][j] = 0.f;
    __syncthreads();

    for (int jt = 0; jt <= qt; ++jt) {
        const int kvbase = jt * 64;
        for (int f = tid; f < 64 * 16; f += 256) {
            int row = f >> 4, dc = (f & 15) * 4;
            float4 tk = *reinterpret_cast<const float4*>(kb + (size_t)(kvbase + row) * TC + dc);
            float* dk = Ks + row * 65 + dc;
            dk[0] = tk.x; dk[1] = tk.y; dk[2] = tk.z; dk[3] = tk.w;
            float4 tv = *reinterpret_cast<const float4*>(vb + (size_t)(kvbase + row) * TC + dc);
            *reinterpret_cast<float4*>(Vs + row * 64 + dc) = tv;
        }
        __syncthreads();

        float s[4][4];
        #pragma unroll
        for (int i = 0; i < 4; i++)
            #pragma unroll
            for (int j = 0; j < 4; j++) s[i][j] = 0.f;

        #pragma unroll 8
        for (int dd = 0; dd < 64; ++dd) {
            float qv[4], kv[4];
            #pragma unroll
            for (int i = 0; i < 4; i++) qv[i] = Qs[(r0 + i) * 65 + dd];
            #pragma unroll
            for (int j = 0; j < 4; j++) kv[j] = Ks[(c0 + j) * 65 + dd];
            #pragma unroll
            for (int i = 0; i < 4; i++)
                #pragma unroll
                for (int j = 0; j < 4; j++)
                    s[i][j] = fmaf(qv[i], kv[j], s[i][j]);
        }

        if (jt == qt) {
            #pragma unroll
            for (int i = 0; i < 4; i++)
                #pragma unroll
                for (int j = 0; j < 4; j++)
                    if (c0 + j > r0 + i) s[i][j] = -3.0e38f;
        }

        #pragma unroll
        for (int i = 0; i < 4; i++) {
            float mx = fmaxf(fmaxf(s[i][0], s[i][1]), fmaxf(s[i][2], s[i][3]));
            red[r0 + i][tx] = mx;
        }
        __syncthreads();
        if (tid < 64) {
            float mx = red[tid][0];
            #pragma unroll
            for (int j = 1; j < 16; j++) mx = fmaxf(mx, red[tid][j]);
            float mn = fmaxf(m_s[tid], mx);
            alpha_s[tid] = __expf(m_s[tid] - mn);
            m_s[tid] = mn;
        }
        __syncthreads();

        #pragma unroll
        for (int i = 0; i < 4; i++) {
            float mr = m_s[r0 + i];
            float rs = 0.f;
            #pragma unroll
            for (int j = 0; j < 4; j++) {
                float p = __expf(s[i][j] - mr);
                Ps[(r0 + i) * 65 + c0 + j] = p;
                rs += p;
            }
            red[r0 + i][tx] = rs;
        }
        __syncthreads();
        if (tid < 64) {
            float sum = 0.f;
            #pragma unroll
            for (int j = 0; j < 16; j++) sum += red[tid][j];
            l_s[tid] = l_s[tid] * alpha_s[tid] + sum;
        }

        float al[4];
        #pragma unroll
        for (int i = 0; i < 4; i++) al[i] = alpha_s[r0 + i];
        #pragma unroll
        for (int i = 0; i < 4; i++)
            #pragma unroll
            for (int j = 0; j < 4; j++) o[i][j] *= al[i];

        #pragma unroll 8
        for (int ss = 0; ss < 64; ++ss) {
            float pv[4], vv[4];
            #pragma unroll
            for (int i = 0; i < 4; i++) pv[i] = Ps[(r0 + i) * 65 + ss];
            #pragma unroll
            for (int j = 0; j < 4; j++) vv[j] = Vs[ss * 64 + c0 + j];
            #pragma unroll
            for (int i = 0; i < 4; i++)
                #pragma unroll
                for (int j = 0; j < 4; j++)
                    o[i][j] = fmaf(pv[i], vv[j], o[i][j]);
        }
        __syncthreads();
    }

    float* ob = O + (size_t)b * TT * TC + (size_t)h * 64;
    #pragma unroll
    for (int i = 0; i < 4; i++) {
        float inv = 1.f / l_s[r0 + i];
        #pragma unroll
        for (int j = 0; j < 4; j++)
            ob[(size_t)(qbase + r0 + i) * TC + c0 + j] = o[i][j] * inv;
    }
}

// ---------------------------------------------------------------------------
// LayerNorm — unchanged from passing round-3 kernel
// ---------------------------------------------------------------------------
__global__ __launch_bounds__(256)
void ln_kernel(const float* __restrict__ in, float* __restrict__ out,
               const float* __restrict__ g, const float* __restrict__ bta)
{
    const int row = blockIdx.x;
    const int tid = threadIdx.x;
    const float* xr = in + (size_t)row * TC;

    float4 v = *reinterpret_cast<const float4*>(xr + tid * 4);
    float s = v.x + v.y + v.z + v.w;

    __shared__ float sred[8];
    __shared__ float s_mu, s_inv;

    #pragma unroll
    for (int o = 16; o > 0; o >>= 1) s += __shfl_xor_sync(0xffffffffu, s, o);
    if ((tid & 31) == 0) sred[tid >> 5] = s;
    __syncthreads();
    if (tid == 0) {
        float t = 0.f;
        #pragma unroll
        for (int i = 0; i < 8; i++) t += sred[i];
        s_mu = t * (1.f / TC);
    }
    __syncthreads();
    const float mu = s_mu;

    float dx = v.x - mu, dy = v.y - mu, dz = v.z - mu, dw = v.w - mu;
    float q = dx * dx + dy * dy + dz * dz + dw * dw;
    #pragma unroll
    for (int o = 16; o > 0; o >>= 1) q += __shfl_xor_sync(0xffffffffu, q, o);
    if ((tid & 31) == 0) sred[tid >> 5] = q;
    __syncthreads();
    if (tid == 0) {
        float t = 0.f;
        #pragma unroll
        for (int i = 0; i < 8; i++) t += sred[i];
        s_inv = rsqrtf(t * (1.f / TC) + 1e-5f);
    }
    __syncthreads();
    const float inv = s_inv;

    float4 gg = *reinterpret_cast<const float4*>(g   + tid * 4);
    float4 bb = *reinterpret_cast<const float4*>(bta + tid * 4);
    float4 r;
    r.x = dx * inv * gg.x + bb.x;
    r.y = dy * inv * gg.y + bb.y;
    r.z = dz * inv * gg.z + bb.z;
    r.w = dw * inv * gg.w + bb.w;
    *reinterpret_cast<float4*>(out + (size_t)row * TC + tid * 4) = r;
}

// ---------------------------------------------------------------------------
extern "C" void kernel_launch(void* const* d_in, const int* in_sizes, int n_in,
                              void* d_out, int out_size)
{
    const float* x   = (const float*)d_in[0];
    const float* Wq  = (const float*)d_in[1];
    const float* Wk  = (const float*)d_in[2];
    const float* Wv  = (const float*)d_in[3];
    const float* Wp  = (const float*)d_in[4];
    const float* bp  = (const float*)d_in[5];
    const float* W1  = (const float*)d_in[6];
    const float* b1  = (const float*)d_in[7];
    const float* W2  = (const float*)d_in[8];
    const float* b2  = (const float*)d_in[9];
    const float* g1  = (const float*)d_in[10];
    const float* be1 = (const float*)d_in[11];
    const float* g2  = (const float*)d_in[12];
    const float* be2 = (const float*)d_in[13];

    float *q, *k, *v, *ocat, *x1, *t2, *hbuf;
    cudaGetSymbolAddress((void**)&q,    g_q);
    cudaGetSymbolAddress((void**)&k,    g_k);
    cudaGetSymbolAddress((void**)&v,    g_v);
    cudaGetSymbolAddress((void**)&ocat, g_ocat);
    cudaGetSymbolAddress((void**)&x1,   g_x1);
    cudaGetSymbolAddress((void**)&t2,   g_t2);
    cudaGetSymbolAddress((void**)&hbuf, g_hbuf);

    __nv_bfloat16 *xh, *xl, *oh, *ol, *x1h, *x1l, *hh, *hl;
    __nv_bfloat16 *wqh, *wql, *wkh, *wkl, *wvh, *wvl, *wph, *wpl, *w1h, *w1l, *w2h, *w2l;
    cudaGetSymbolAddress((void**)&xh,  g_xh);   cudaGetSymbolAddress((void**)&xl,  g_xl);
    cudaGetSymbolAddress((void**)&oh,  g_oh);   cudaGetSymbolAddress((void**)&ol,  g_ol);
    cudaGetSymbolAddress((void**)&x1h, g_x1h);  cudaGetSymbolAddress((void**)&x1l, g_x1l);
    cudaGetSymbolAddress((void**)&hh,  g_hh);   cudaGetSymbolAddress((void**)&hl,  g_hl);
    cudaGetSymbolAddress((void**)&wqh, g_wqh);  cudaGetSymbolAddress((void**)&wql, g_wql);
    cudaGetSymbolAddress((void**)&wkh, g_wkh);  cudaGetSymbolAddress((void**)&wkl, g_wkl);
    cudaGetSymbolAddress((void**)&wvh, g_wvh);  cudaGetSymbolAddress((void**)&wvl, g_wvl);
    cudaGetSymbolAddress((void**)&wph, g_wph);  cudaGetSymbolAddress((void**)&wpl, g_wpl);
    cudaGetSymbolAddress((void**)&w1h, g_w1h);  cudaGetSymbolAddress((void**)&w1l, g_w1l);
    cudaGetSymbolAddress((void**)&w2h, g_w2h);  cudaGetSymbolAddress((void**)&w2l, g_w2l);

    const int attn_smem = ATTN_SMEM_FLOATS * (int)sizeof(float);
    cudaFuncSetAttribute(attn_kernel, cudaFuncAttributeMaxDynamicSharedMemorySize, attn_smem);
    cudaFuncSetAttribute(gemm_bf3, cudaFuncAttributeMaxDynamicSharedMemorySize, GSMEM_BYTES);
    cudaFuncSetAttribute(qkv_bf3,  cudaFuncAttributeMaxDynamicSharedMemorySize, GSMEM_BYTES);

    dim3 blk(256);
    dim3 gT(TC / 32, TC / 32);
    dim3 gT1(FF / 32, TC / 32);
    dim3 gT2(TC / 32, FF / 32);

    // Weight transpose + bf16 split
    transpose_split<true ><<<gT,  blk>>>(Wq, wqh, wql, TC, TC);
    transpose_split<true ><<<gT,  blk>>>(Wk, wkh, wkl, TC, TC);
    transpose_split<true ><<<gT,  blk>>>(Wv, wvh, wvl, TC, TC);
    transpose_split<false><<<gT,  blk>>>(Wp, wph, wpl, TC, TC);
    transpose_split<false><<<gT1, blk>>>(W1, w1h, w1l, TC, FF);
    transpose_split<false><<<gT2, blk>>>(W2, w2h, w2l, FF, TC);

    // Activation split: x
    cvt_split<<<ACT / 1024, blk>>>(x, xh, xl, ACT / 4);

    // QKV (fused over grid.z)
    dim3 gQKV(TC / 128, BT_ROWS / 128, 3);
    qkv_bf3<<<gQKV, blk, GSMEM_BYTES>>>(xh, xl, wqh, wql, wkh, wkl, wvh, wvl, q, k, v);

    // Causal attention (fp32)
    dim3 gA(TT / 64, TH, TB);
    attn_kernel<<<gA, blk, attn_smem>>>(q, k, v, ocat);

    // Output projection + bias + residual(x)
    cvt_split<<<ACT / 1024, blk>>>(ocat, oh, ol, ACT / 4);
    dim3 gC(TC / 128, BT_ROWS / 128);
    gemm_bf3<<<gC, blk, GSMEM_BYTES>>>(oh, ol, wph, wpl, t2, TC, TC, bp, x, 0);

    // LN1
    ln_kernel<<<BT_ROWS, blk>>>(t2, x1, g1, be1);

    // FFN
    cvt_split<<<ACT / 1024, blk>>>(x1, x1h, x1l, ACT / 4);
    dim3 gF(FF / 128, BT_ROWS / 128);
    gemm_bf3<<<gF, blk, GSMEM_BYTES>>>(x1h, x1l, w1h, w1l, hbuf, FF, TC, b1, nullptr, 1);
    cvt_split<<<(BT_ROWS / 1024) * FF, blk>>>(hbuf, hh, hl, (int)((size_t)BT_ROWS * FF / 4));
    gemm_bf3<<<gC, blk, GSMEM_BYTES>>>(hh, hl, w2h, w2l, t2, TC, FF, b2, x1, 0);

    // LN2 -> output
    ln_kernel<<<BT_ROWS, blk>>>(t2, (float*)d_out, g2, be2);
}